// round 16
// baseline (speedup 1.0000x reference)
#include <cuda_runtime.h>
#include <cuda_fp16.h>
#include <math.h>
#include <stdint.h>

// ---------------- problem constants ----------------
#define M_TOK   65536
#define KCODE   1024
#define BM      64            // tokens per CTA
#define BN      64            // codes per chunk
#define NCHUNK  16
#define GRID_MAIN 1024
#define MARGIN  0.25f
#define NCAND   24            // 8 threads x top-3 per token

// Output layout (floats): [z_q | similarity | ids | loss]
#define SIM_OFF   8388608ULL
#define IDSG_OFF  75497472ULL
#define LOSS_OFF  75563008ULL

// ---------------- smem layout (byte offsets) ----------------
#define A_OFF      0              // z fp16: 64 rows x 256B = 16384 (dead after loop)
#define STAGE_OFF  16384          // 8 warps x 16 rows x 144B = 18432
#define STAGE_W    2304           // per-warp stage bytes
#define STAGE_P    144            // stage row pitch (multiple of 16)
#define NE_OFF     34816          // 4096
#define RE_OFF     38912          // 4096
#define NZ_OFF     43008          // 256
#define RZ_OFF     43264          // 256
#define IDS_SM     43520          // 256
#define LT_SM      43776          // 256
#define SMEM_BYTES 44032          // x4 CTAs = 176128 <= 228KB carveout

// post-loop overlays (A region dead after main loop)
#define REDD_OFF   0              // 64 tok x 24 cand dists = 6144
#define REDI_OFF   6144           // 64 tok x 24 cand idx   = 6144

// ---------------- device scratch ----------------
// fp16 codebook in EXACT mma-fragment order (unchanged from R14):
//   g_Eb[((chunk*8 + kk)*8 + nblock)*32 + lane] = { b0, b1 } (uint2)
__device__ __align__(16) uint2 g_Eb[NCHUNK * 8 * 8 * 32];
__device__ float g_ne[KCODE];
__device__ float g_re[KCODE];
__device__ float g_partial[GRID_MAIN];
__device__ unsigned g_done = 0;   // last-CTA counter (self-resetting each pass)

// ---------------- PTX helpers (baseline ISA only) ----------------
__device__ __forceinline__ uint32_t smem_u32(const void* p) {
    uint32_t a;
    asm("{ .reg .u64 t; cvta.to.shared.u64 t, %1; cvt.u32.u64 %0, t; }" : "=r"(a) : "l"(p));
    return a;
}
__device__ __forceinline__ void ldsm_x4(uint32_t& r0, uint32_t& r1, uint32_t& r2, uint32_t& r3,
                                        uint32_t addr) {
    asm volatile("ldmatrix.sync.aligned.m8n8.x4.shared.b16 {%0,%1,%2,%3}, [%4];"
                 : "=r"(r0), "=r"(r1), "=r"(r2), "=r"(r3) : "r"(addr));
}
__device__ __forceinline__ void mma_f16(float* c, const uint32_t* a, const uint32_t* b) {
    asm volatile("mma.sync.aligned.m16n8k16.row.col.f32.f16.f16.f32 "
                 "{%0,%1,%2,%3}, {%4,%5,%6,%7}, {%8,%9}, {%0,%1,%2,%3};"
                 : "+f"(c[0]), "+f"(c[1]), "+f"(c[2]), "+f"(c[3])
                 : "r"(a[0]), "r"(a[1]), "r"(a[2]), "r"(a[3]), "r"(b[0]), "r"(b[1]));
}
// streaming (evict-first) stores: sim/zq/ids are write-once data
__device__ __forceinline__ void stg_cs_f4(float* p, float4 v) {
    asm volatile("st.global.cs.v4.f32 [%0], {%1,%2,%3,%4};"
                 :: "l"(p), "f"(v.x), "f"(v.y), "f"(v.z), "f"(v.w) : "memory");
}
__device__ __forceinline__ void stg_cs_f1(float* p, float v) {
    asm volatile("st.global.cs.f32 [%0], %1;" :: "l"(p), "f"(v) : "memory");
}

// ---------------- codebook prep: fp16 convert + norms + fragment order ------
__global__ void prep_e(const float* __restrict__ E) {
    int row  = blockIdx.x * 8 + (threadIdx.x >> 5);   // global code id
    int lane = threadIdx.x & 31;
    float4 v = reinterpret_cast<const float4*>(E)[(size_t)row * 32 + lane];
    float s = fmaf(v.x, v.x, fmaf(v.y, v.y, fmaf(v.z, v.z, v.w * v.w)));
#pragma unroll
    for (int m = 16; m; m >>= 1) s += __shfl_xor_sync(0xffffffffu, s, m);
    if (lane == 0) { g_ne[row] = s; g_re[row] = rsqrtf(s); }

    __half2 hA = __halves2half2(__float2half_rn(v.x), __float2half_rn(v.y));
    __half2 hB = __halves2half2(__float2half_rn(v.z), __float2half_rn(v.w));
    uint32_t wA = *reinterpret_cast<uint32_t*>(&hA);
    uint32_t wB = *reinterpret_cast<uint32_t*>(&hB);

    const int c    = row >> 6;        // chunk
    const int nloc = row & 63;
    const int nb   = nloc >> 3;       // n-block
    const int Tn   = nloc & 7;        // lane group within block
    uint32_t* Eb32 = reinterpret_cast<uint32_t*>(g_Eb);
#pragma unroll
    for (int j2 = 0; j2 < 2; ++j2) {
        int h0 = 4 * lane + j2 * 2;
        int kk = h0 >> 4;
        int hh = h0 & 15;
        int b  = hh >> 3;
        int tk = (hh & 7) >> 1;
        int T  = Tn * 4 + tk;
        int idx = (((c * 8 + kk) * 8 + nb) * 32 + T) * 2 + b;
        Eb32[idx] = j2 ? wB : wA;
    }
}

// ---------------- main fused kernel (warp-independent main loop) ------------
__global__ __launch_bounds__(256, 4)
void vq_main(const float* __restrict__ Z, const float* __restrict__ E,
             float* __restrict__ out) {
    extern __shared__ char sb[];
    const uint32_t sbase = smem_u32(sb);

    const int tid  = threadIdx.x;
    const int lane = tid & 31;
    const int warp = tid >> 5;
    const int wq   = warp & 3;       // m-quarter: rows wq*16 .. +15
    const int wn   = warp >> 2;      // n-half: cols wn*32 .. +31
    const int qrow = lane >> 2;
    const int qcol = lane & 3;
    const int m0   = blockIdx.x * BM;

    float* ne_sm = (float*)(sb + NE_OFF);
    float* re_sm = (float*)(sb + RE_OFF);
    float* nz_sm = (float*)(sb + NZ_OFF);
    float* rz_sm = (float*)(sb + RZ_OFF);
    int*   ids_sm = (int*)(sb + IDS_SM);
    float* lt_sm  = (float*)(sb + LT_SM);

    float* zq   = out;
    float* sim  = out + SIM_OFF;
    float* idsf = out + IDSG_OFF;

    // codebook norms into smem
    for (int i = tid; i < KCODE; i += 256) { ne_sm[i] = g_ne[i]; re_sm[i] = g_re[i]; }

    // A prologue: thread = (row, k-quarter); fp32 norm + fp16 convert (Z read once here)
    {
        const int row = tid >> 2, kh = tid & 3;
        const float4* Zr = reinterpret_cast<const float4*>(
            Z + (size_t)(m0 + row) * 128 + kh * 32);
        float nzp = 0.f;
        uint32_t p1[16];
#pragma unroll
        for (int g = 0; g < 4; ++g) {
            float4 v0 = Zr[2 * g], v1 = Zr[2 * g + 1];
            nzp = fmaf(v0.x, v0.x, fmaf(v0.y, v0.y, fmaf(v0.z, v0.z, fmaf(v0.w, v0.w, nzp))));
            nzp = fmaf(v1.x, v1.x, fmaf(v1.y, v1.y, fmaf(v1.z, v1.z, fmaf(v1.w, v1.w, nzp))));
            __half2 h0 = __halves2half2(__float2half_rn(v0.x), __float2half_rn(v0.y));
            __half2 h1 = __halves2half2(__float2half_rn(v0.z), __float2half_rn(v0.w));
            __half2 h2 = __halves2half2(__float2half_rn(v1.x), __float2half_rn(v1.y));
            __half2 h3 = __halves2half2(__float2half_rn(v1.z), __float2half_rn(v1.w));
            p1[4 * g + 0] = *reinterpret_cast<uint32_t*>(&h0);
            p1[4 * g + 1] = *reinterpret_cast<uint32_t*>(&h1);
            p1[4 * g + 2] = *reinterpret_cast<uint32_t*>(&h2);
            p1[4 * g + 3] = *reinterpret_cast<uint32_t*>(&h3);
        }
#pragma unroll
        for (int q = 0; q < 4; ++q) {
            uint32_t u   = (uint32_t)(kh * 4 + q);
            uint32_t off = (uint32_t)row * 256u + (((u ^ (uint32_t)(row & 7))) << 4);
            *(uint4*)(sb + A_OFF + off) = make_uint4(p1[4*q], p1[4*q+1], p1[4*q+2], p1[4*q+3]);
        }
        nzp += __shfl_xor_sync(0xffffffffu, nzp, 1);
        nzp += __shfl_xor_sync(0xffffffffu, nzp, 2);
        if (kh == 0) { nz_sm[row] = nzp; rz_sm[row] = rsqrtf(nzp); }
    }
    __syncthreads();   // ONLY CTA barrier before/inside main loop

    // per-thread row constants (2 rows: qrow and qrow+8 of this m-quarter)
    const int r0g = wq * 16 + qrow;      // CTA-local token row 0
    const int r1g = r0g + 8;             // CTA-local token row 1
    const float nzA = nz_sm[r0g], rzA = rz_sm[r0g];
    const float nzB = nz_sm[r1g], rzB = rz_sm[r1g];

    // per-thread TOP-3 (dist, idx) per row
    float bA1 = 3.4e38f, bA2 = 3.4e38f, bA3 = 3.4e38f;
    float bB1 = 3.4e38f, bB2 = 3.4e38f, bB3 = 3.4e38f;
    int   iA1 = 0, iA2 = 0, iA3 = 0, iB1 = 0, iB2 = 0, iB3 = 0;

    const int sel = lane >> 3;
    const uint2* __restrict__ Eb = g_Eb;
    const uint32_t stage = sbase + STAGE_OFF + (uint32_t)warp * STAGE_W;

#define TOP3(b1,b2,b3,i1,i2,i3,dd,ii)                                   \
    if ((dd) < (b3)) {                                                  \
        if ((dd) < (b2)) {                                              \
            (b3)=(b2); (i3)=(i2);                                       \
            if ((dd) < (b1)) { (b2)=(b1); (i2)=(i1); (b1)=(dd); (i1)=(ii); } \
            else             { (b2)=(dd); (i2)=(ii); }                  \
        } else { (b3)=(dd); (i3)=(ii); }                                \
    }

#pragma unroll 1
    for (int t = 0; t < NCHUNK; ++t) {
        float acc[4][4];
#pragma unroll
        for (int nf = 0; nf < 4; ++nf)
#pragma unroll
            for (int q = 0; q < 4; ++q) acc[nf][q] = 0.f;

        // single-product fp16 GEMM: A (16 rows) from smem LDSM, B fragments via LDG
#pragma unroll
        for (int kk = 0; kk < 8; ++kk) {
            const uint32_t cu = (uint32_t)(kk * 2 + (sel >> 1));
            const int r = wq * 16 + (sel & 1) * 8 + (lane & 7);
            uint32_t addr = sbase + A_OFF + (uint32_t)r * 256u
                          + (((cu ^ (uint32_t)(r & 7))) << 4);
            uint32_t a[4];
            ldsm_x4(a[0], a[1], a[2], a[3], addr);
#pragma unroll
            for (int nf = 0; nf < 4; ++nf) {
                uint2 w = __ldg(&Eb[((t * 8 + kk) * 8 + wn * 4 + nf) * 32 + lane]);
                uint32_t bf[2] = { w.x, w.y };
                mma_f16(acc[nf], a, bf);
            }
        }

        // ---- epilogue: dist -> top-3 + sim into warp-private stage ----
#pragma unroll
        for (int nf = 0; nf < 4; ++nf) {
            const int ccl = nf * 8 + qcol * 2;           // warp-local col 0..31
            const int nc  = t * BN + wn * 32 + ccl;      // global code
            float2 ne2 = *reinterpret_cast<const float2*>(ne_sm + nc);
            float2 re2 = *reinterpret_cast<const float2*>(re_sm + nc);
            // row qrow
            {
                float d0 = acc[nf][0], d1 = acc[nf][1];
                float dd0 = fmaf(-2.f, d0, nzA) + ne2.x;
                float dd1 = fmaf(-2.f, d1, nzA) + ne2.y;
                TOP3(bA1,bA2,bA3,iA1,iA2,iA3, dd0, nc)
                TOP3(bA1,bA2,bA3,iA1,iA2,iA3, dd1, nc + 1)
                *reinterpret_cast<float2*>(sb + (stage - sbase) + qrow * STAGE_P + ccl * 4) =
                    make_float2(d0 * rzA * re2.x, d1 * rzA * re2.y);
            }
            // row qrow + 8
            {
                float d0 = acc[nf][2], d1 = acc[nf][3];
                float dd0 = fmaf(-2.f, d0, nzB) + ne2.x;
                float dd1 = fmaf(-2.f, d1, nzB) + ne2.y;
                TOP3(bB1,bB2,bB3,iB1,iB2,iB3, dd0, nc)
                TOP3(bB1,bB2,bB3,iB1,iB2,iB3, dd1, nc + 1)
                *reinterpret_cast<float2*>(sb + (stage - sbase) + (qrow + 8) * STAGE_P + ccl * 4) =
                    make_float2(d0 * rzB * re2.x, d1 * rzB * re2.y);
            }
        }
        __syncwarp();

        // ---- flush warp stage: STG.128, 4 rows x 128B per instruction ----
        {
            const int fr = lane >> 3;            // row group 0..3
            const int fu = lane & 7;             // 16B unit within 128B
#pragma unroll
            for (int it = 0; it < 4; ++it) {
                const int rl = it * 4 + fr;      // warp-local row 0..15
                float4 v = *reinterpret_cast<const float4*>(
                    sb + (stage - sbase) + rl * STAGE_P + fu * 16);
                stg_cs_f4(sim + (size_t)(m0 + wq * 16 + rl) * 1024
                              + t * BN + wn * 32 + fu * 4, v);
            }
        }
        __syncwarp();
    }

    // ---- all warps done: A region dead; dump top-3 candidates there ----
    __syncthreads();
    float* redD = (float*)(sb + REDD_OFF);
    int*   redI = (int*)(sb + REDI_OFF);
    {
        const int slot = (wn * 4 + qcol) * 3;    // 8 threads x 3 entries per token
        int baseA = r0g * NCAND + slot;
        int baseB = r1g * NCAND + slot;
        redD[baseA] = bA1; redI[baseA] = iA1;
        redD[baseA + 1] = bA2; redI[baseA + 1] = iA2;
        redD[baseA + 2] = bA3; redI[baseA + 2] = iA3;
        redD[baseB] = bB1; redI[baseB] = iB1;
        redD[baseB + 1] = bB2; redI[baseB + 1] = iB2;
        redD[baseB + 2] = bB3; redI[baseB + 2] = iB3;
    }
    __syncthreads();

    // ---- exact fp32 refine: one thread per token (Z row via L1/L2) ----
    if (tid < BM) {
        const int tok = tid;
        float m1 = 3.4e38f;
#pragma unroll
        for (int e = 0; e < NCAND; ++e) m1 = fminf(m1, redD[tok * NCAND + e]);
        const float thr = m1 + MARGIN;
        const float nzt = nz_sm[tok];
        const float4* Zr = reinterpret_cast<const float4*>(Z) + (size_t)(m0 + tok) * 32;
        float bestd = 3.4e38f; int besti = KCODE;
        for (int e = 0; e < NCAND; ++e) {
            if (redD[tok * NCAND + e] <= thr) {
                const int id = redI[tok * NCAND + e];
                const float4* Er = reinterpret_cast<const float4*>(E) + (size_t)id * 32;
                float dot = 0.f;
#pragma unroll
                for (int q = 0; q < 32; ++q) {
                    float4 a = Zr[q], b = Er[q];
                    dot = fmaf(a.x, b.x, fmaf(a.y, b.y, fmaf(a.z, b.z, fmaf(a.w, b.w, dot))));
                }
                float de = fmaf(-2.f, dot, nzt) + ne_sm[id];   // reference association order
                if (de < bestd || (de == bestd && id < besti)) { bestd = de; besti = id; }
            }
        }
        ids_sm[tok] = besti;
        stg_cs_f1(idsf + m0 + tok, (float)besti);
        lt_sm[tok] = sqrtf(fmaxf(bestd, 0.f));   // ||z - z_q||^2 == dist_min exactly
    }
    __syncthreads();

    // z_q gather (codebook is L2-resident), streaming stores
    const float4* E4 = reinterpret_cast<const float4*>(E);
#pragma unroll
    for (int rr = 0; rr < 8; ++rr) {
        int ml = warp * 8 + rr;
        int id = ids_sm[ml];
        stg_cs_f4(zq + ((size_t)(m0 + ml) * 32 + lane) * 4, E4[(size_t)id * 32 + lane]);
    }

    // deterministic per-block loss partial (fixed serial order)
    if (tid == 0) {
        float s = 0.f;
        for (int i = 0; i < BM; ++i) s += lt_sm[i];
        g_partial[blockIdx.x] = s;
    }

    // ---- merged loss reduction: last CTA sums all partials (fixed tree) ----
    __shared__ int is_last;
    __threadfence();
    if (tid == 0) {
        unsigned old = atomicAdd(&g_done, 1u);
        is_last = (old == GRID_MAIN - 1) ? 1 : 0;
    }
    __syncthreads();
    if (is_last) {
        __threadfence();
        float* red = (float*)(sb + REDD_OFF);   // reuse candidate area
        float s = g_partial[tid] + g_partial[tid + 256]
                + g_partial[tid + 512] + g_partial[tid + 768];
        red[tid] = s;
        __syncthreads();
#pragma unroll
        for (int st = 128; st > 0; st >>= 1) {
            if (tid < st) red[tid] += red[tid + st];
            __syncthreads();
        }
        if (tid == 0) {
            out[LOSS_OFF] = 1.25f * (red[0] * (1.f / 65536.f));
            g_done = 0;   // reset for the next graph replay
        }
    }
}

extern "C" void kernel_launch(void* const* d_in, const int* in_sizes, int n_in,
                              void* d_out, int out_size) {
    (void)in_sizes; (void)n_in; (void)out_size;
    const float* Z = (const float*)d_in[0];   // z_e            [65536, 128]
    const float* E = (const float*)d_in[1];   // vecs_embedding [1024, 128]
    float* out = (float*)d_out;

    cudaFuncSetAttribute((const void*)vq_main,
                         cudaFuncAttributeMaxDynamicSharedMemorySize, SMEM_BYTES);

    prep_e<<<KCODE / 8, 256>>>(E);
    vq_main<<<GRID_MAIN, 256, SMEM_BYTES>>>(Z, E, out);
}

// round 17
// speedup vs baseline: 1.5977x; 1.5977x over previous
#include <cuda_runtime.h>
#include <cuda_fp16.h>
#include <math.h>
#include <stdint.h>

// ---------------- problem constants ----------------
#define M_TOK   65536
#define KCODE   1024
#define BM      64            // tokens per CTA
#define BN      64            // codes per chunk
#define NCHUNK  16
#define GRID_MAIN 1024
#define MARGIN  0.25f
#define NCAND   24            // 8 threads x top-3 per token

// Output layout (floats): [z_q | similarity | ids | loss]
#define SIM_OFF   8388608ULL
#define IDSG_OFF  75497472ULL
#define LOSS_OFF  75563008ULL

// ---------------- smem layout (byte offsets) ----------------
#define A_OFF      0              // z fp16: 64 rows x 256B = 16384 (dead after loop)
#define STAGE_OFF  16384          // 8 warps x 16 rows x 144B = 18432
#define STAGE_W    2304           // per-warp stage bytes
#define STAGE_P    144            // stage row pitch (multiple of 16)
#define NE_OFF     34816          // 4096
#define RE_OFF     38912          // 4096
#define NZ_OFF     43008          // 256
#define RZ_OFF     43264          // 256
#define IDS_SM     43520          // 256
#define LT_SM      43776          // 256
#define SMEM_BYTES 44032          // x3 CTAs = 132096 <= 228KB carveout

// post-loop overlays (A region dead after main loop)
#define REDD_OFF   0              // 64 tok x 24 cand dists = 6144
#define REDI_OFF   6144           // 64 tok x 24 cand idx   = 6144

// ---------------- device scratch ----------------
// fp16 codebook in EXACT mma-fragment order (unchanged from R14):
//   g_Eb[((chunk*8 + kk)*8 + nblock)*32 + lane] = { b0, b1 } (uint2)
__device__ __align__(16) uint2 g_Eb[NCHUNK * 8 * 8 * 32];
__device__ float g_ne[KCODE];
__device__ float g_re[KCODE];
__device__ float g_partial[GRID_MAIN];
__device__ unsigned g_done = 0;   // last-CTA counter (self-resetting each pass)

// ---------------- PTX helpers (baseline ISA only) ----------------
__device__ __forceinline__ uint32_t smem_u32(const void* p) {
    uint32_t a;
    asm("{ .reg .u64 t; cvta.to.shared.u64 t, %1; cvt.u32.u64 %0, t; }" : "=r"(a) : "l"(p));
    return a;
}
__device__ __forceinline__ void ldsm_x4(uint32_t& r0, uint32_t& r1, uint32_t& r2, uint32_t& r3,
                                        uint32_t addr) {
    asm volatile("ldmatrix.sync.aligned.m8n8.x4.shared.b16 {%0,%1,%2,%3}, [%4];"
                 : "=r"(r0), "=r"(r1), "=r"(r2), "=r"(r3) : "r"(addr));
}
__device__ __forceinline__ void mma_f16(float* c, const uint32_t* a, const uint32_t* b) {
    asm volatile("mma.sync.aligned.m16n8k16.row.col.f32.f16.f16.f32 "
                 "{%0,%1,%2,%3}, {%4,%5,%6,%7}, {%8,%9}, {%0,%1,%2,%3};"
                 : "+f"(c[0]), "+f"(c[1]), "+f"(c[2]), "+f"(c[3])
                 : "r"(a[0]), "r"(a[1]), "r"(a[2]), "r"(a[3]), "r"(b[0]), "r"(b[1]));
}
// streaming (evict-first) stores: sim/zq/ids are write-once data
__device__ __forceinline__ void stg_cs_f4(float* p, float4 v) {
    asm volatile("st.global.cs.v4.f32 [%0], {%1,%2,%3,%4};"
                 :: "l"(p), "f"(v.x), "f"(v.y), "f"(v.z), "f"(v.w) : "memory");
}
__device__ __forceinline__ void stg_cs_f1(float* p, float v) {
    asm volatile("st.global.cs.f32 [%0], %1;" :: "l"(p), "f"(v) : "memory");
}

// ---------------- codebook prep: fp16 convert + norms + fragment order ------
__global__ void prep_e(const float* __restrict__ E) {
    int row  = blockIdx.x * 8 + (threadIdx.x >> 5);   // global code id
    int lane = threadIdx.x & 31;
    float4 v = reinterpret_cast<const float4*>(E)[(size_t)row * 32 + lane];
    float s = fmaf(v.x, v.x, fmaf(v.y, v.y, fmaf(v.z, v.z, v.w * v.w)));
#pragma unroll
    for (int m = 16; m; m >>= 1) s += __shfl_xor_sync(0xffffffffu, s, m);
    if (lane == 0) { g_ne[row] = s; g_re[row] = rsqrtf(s); }

    __half2 hA = __halves2half2(__float2half_rn(v.x), __float2half_rn(v.y));
    __half2 hB = __halves2half2(__float2half_rn(v.z), __float2half_rn(v.w));
    uint32_t wA = *reinterpret_cast<uint32_t*>(&hA);
    uint32_t wB = *reinterpret_cast<uint32_t*>(&hB);

    const int c    = row >> 6;        // chunk
    const int nloc = row & 63;
    const int nb   = nloc >> 3;       // n-block
    const int Tn   = nloc & 7;        // lane group within block
    uint32_t* Eb32 = reinterpret_cast<uint32_t*>(g_Eb);
#pragma unroll
    for (int j2 = 0; j2 < 2; ++j2) {
        int h0 = 4 * lane + j2 * 2;
        int kk = h0 >> 4;
        int hh = h0 & 15;
        int b  = hh >> 3;
        int tk = (hh & 7) >> 1;
        int T  = Tn * 4 + tk;
        int idx = (((c * 8 + kk) * 8 + nb) * 32 + T) * 2 + b;
        Eb32[idx] = j2 ? wB : wA;
    }
}

// ---------------- main fused kernel (warp-independent main loop) ------------
__global__ __launch_bounds__(256, 3)      // 3 CTAs: ~85 regs available, NO SPILLS
void vq_main(const float* __restrict__ Z, const float* __restrict__ E,
             float* __restrict__ out) {
    extern __shared__ char sb[];
    const uint32_t sbase = smem_u32(sb);

    const int tid  = threadIdx.x;
    const int lane = tid & 31;
    const int warp = tid >> 5;
    const int wq   = warp & 3;       // m-quarter: rows wq*16 .. +15
    const int wn   = warp >> 2;      // n-half: cols wn*32 .. +31
    const int qrow = lane >> 2;
    const int qcol = lane & 3;
    const int m0   = blockIdx.x * BM;

    float* ne_sm = (float*)(sb + NE_OFF);
    float* re_sm = (float*)(sb + RE_OFF);
    float* nz_sm = (float*)(sb + NZ_OFF);
    float* rz_sm = (float*)(sb + RZ_OFF);
    int*   ids_sm = (int*)(sb + IDS_SM);
    float* lt_sm  = (float*)(sb + LT_SM);

    float* zq   = out;
    float* sim  = out + SIM_OFF;
    float* idsf = out + IDSG_OFF;

    // codebook norms into smem
    for (int i = tid; i < KCODE; i += 256) { ne_sm[i] = g_ne[i]; re_sm[i] = g_re[i]; }

    // A prologue: thread = (row, k-quarter); fp32 norm + fp16 convert (Z read once)
    {
        const int row = tid >> 2, kh = tid & 3;
        const float4* Zr = reinterpret_cast<const float4*>(
            Z + (size_t)(m0 + row) * 128 + kh * 32);
        float nzp = 0.f;
        uint32_t p1[16];
#pragma unroll
        for (int g = 0; g < 4; ++g) {
            float4 v0 = Zr[2 * g], v1 = Zr[2 * g + 1];
            nzp = fmaf(v0.x, v0.x, fmaf(v0.y, v0.y, fmaf(v0.z, v0.z, fmaf(v0.w, v0.w, nzp))));
            nzp = fmaf(v1.x, v1.x, fmaf(v1.y, v1.y, fmaf(v1.z, v1.z, fmaf(v1.w, v1.w, nzp))));
            __half2 h0 = __halves2half2(__float2half_rn(v0.x), __float2half_rn(v0.y));
            __half2 h1 = __halves2half2(__float2half_rn(v0.z), __float2half_rn(v0.w));
            __half2 h2 = __halves2half2(__float2half_rn(v1.x), __float2half_rn(v1.y));
            __half2 h3 = __halves2half2(__float2half_rn(v1.z), __float2half_rn(v1.w));
            p1[4 * g + 0] = *reinterpret_cast<uint32_t*>(&h0);
            p1[4 * g + 1] = *reinterpret_cast<uint32_t*>(&h1);
            p1[4 * g + 2] = *reinterpret_cast<uint32_t*>(&h2);
            p1[4 * g + 3] = *reinterpret_cast<uint32_t*>(&h3);
        }
#pragma unroll
        for (int q = 0; q < 4; ++q) {
            uint32_t u   = (uint32_t)(kh * 4 + q);
            uint32_t off = (uint32_t)row * 256u + (((u ^ (uint32_t)(row & 7))) << 4);
            *(uint4*)(sb + A_OFF + off) = make_uint4(p1[4*q], p1[4*q+1], p1[4*q+2], p1[4*q+3]);
        }
        nzp += __shfl_xor_sync(0xffffffffu, nzp, 1);
        nzp += __shfl_xor_sync(0xffffffffu, nzp, 2);
        if (kh == 0) { nz_sm[row] = nzp; rz_sm[row] = rsqrtf(nzp); }
    }
    __syncthreads();   // ONLY CTA barrier before/inside main loop

    // per-thread row constants (2 rows: qrow and qrow+8 of this m-quarter)
    const int r0g = wq * 16 + qrow;
    const int r1g = r0g + 8;
    const float nzA = nz_sm[r0g], rzA = rz_sm[r0g];
    const float nzB = nz_sm[r1g], rzB = rz_sm[r1g];

    // per-thread TOP-3 (dist, idx) per row
    float bA1 = 3.4e38f, bA2 = 3.4e38f, bA3 = 3.4e38f;
    float bB1 = 3.4e38f, bB2 = 3.4e38f, bB3 = 3.4e38f;
    int   iA1 = 0, iA2 = 0, iA3 = 0, iB1 = 0, iB2 = 0, iB3 = 0;

    const int sel = lane >> 3;
    const uint2* __restrict__ Eb = g_Eb;
    const uint32_t stg_off = STAGE_OFF + (uint32_t)warp * STAGE_W;

#define TOP3(b1,b2,b3,i1,i2,i3,dd,ii)                                   \
    if ((dd) < (b3)) {                                                  \
        if ((dd) < (b2)) {                                              \
            (b3)=(b2); (i3)=(i2);                                       \
            if ((dd) < (b1)) { (b2)=(b1); (i2)=(i1); (b1)=(dd); (i1)=(ii); } \
            else             { (b2)=(dd); (i2)=(ii); }                  \
        } else { (b3)=(dd); (i3)=(ii); }                                \
    }

#pragma unroll 1
    for (int t = 0; t < NCHUNK; ++t) {
        float acc[4][4];
#pragma unroll
        for (int nf = 0; nf < 4; ++nf)
#pragma unroll
            for (int q = 0; q < 4; ++q) acc[nf][q] = 0.f;

        // single-product fp16 GEMM: A (16 rows) from smem LDSM, B fragments via LDG
#pragma unroll
        for (int kk = 0; kk < 8; ++kk) {
            const uint32_t cu = (uint32_t)(kk * 2 + (sel >> 1));
            const int r = wq * 16 + (sel & 1) * 8 + (lane & 7);
            uint32_t addr = sbase + A_OFF + (uint32_t)r * 256u
                          + (((cu ^ (uint32_t)(r & 7))) << 4);
            uint32_t a[4];
            ldsm_x4(a[0], a[1], a[2], a[3], addr);
#pragma unroll
            for (int nf = 0; nf < 4; ++nf) {
                uint2 w = __ldg(&Eb[((t * 8 + kk) * 8 + wn * 4 + nf) * 32 + lane]);
                uint32_t bf[2] = { w.x, w.y };
                mma_f16(acc[nf], a, bf);
            }
        }

        // ---- epilogue: dist -> top-3 + sim into warp-private stage ----
#pragma unroll
        for (int nf = 0; nf < 4; ++nf) {
            const int ccl = nf * 8 + qcol * 2;           // warp-local col 0..31
            const int nc  = t * BN + wn * 32 + ccl;      // global code
            float2 ne2 = *reinterpret_cast<const float2*>(ne_sm + nc);
            float2 re2 = *reinterpret_cast<const float2*>(re_sm + nc);
            // row qrow
            {
                float d0 = acc[nf][0], d1 = acc[nf][1];
                float dd0 = fmaf(-2.f, d0, nzA) + ne2.x;
                float dd1 = fmaf(-2.f, d1, nzA) + ne2.y;
                TOP3(bA1,bA2,bA3,iA1,iA2,iA3, dd0, nc)
                TOP3(bA1,bA2,bA3,iA1,iA2,iA3, dd1, nc + 1)
                *reinterpret_cast<float2*>(sb + stg_off + qrow * STAGE_P + ccl * 4) =
                    make_float2(d0 * rzA * re2.x, d1 * rzA * re2.y);
            }
            // row qrow + 8
            {
                float d0 = acc[nf][2], d1 = acc[nf][3];
                float dd0 = fmaf(-2.f, d0, nzB) + ne2.x;
                float dd1 = fmaf(-2.f, d1, nzB) + ne2.y;
                TOP3(bB1,bB2,bB3,iB1,iB2,iB3, dd0, nc)
                TOP3(bB1,bB2,bB3,iB1,iB2,iB3, dd1, nc + 1)
                *reinterpret_cast<float2*>(sb + stg_off + (qrow + 8) * STAGE_P + ccl * 4) =
                    make_float2(d0 * rzB * re2.x, d1 * rzB * re2.y);
            }
        }
        __syncwarp();

        // ---- flush warp stage: STG.128, 4 rows x 128B per instruction ----
        {
            const int fr = lane >> 3;            // row group 0..3
            const int fu = lane & 7;             // 16B unit within 128B
#pragma unroll
            for (int it = 0; it < 4; ++it) {
                const int rl = it * 4 + fr;      // warp-local row 0..15
                float4 v = *reinterpret_cast<const float4*>(
                    sb + stg_off + rl * STAGE_P + fu * 16);
                stg_cs_f4(sim + (size_t)(m0 + wq * 16 + rl) * 1024
                              + t * BN + wn * 32 + fu * 4, v);
            }
        }
        __syncwarp();
    }

    // ---- all warps done: A region dead; dump top-3 candidates there ----
    __syncthreads();
    float* redD = (float*)(sb + REDD_OFF);
    int*   redI = (int*)(sb + REDI_OFF);
    {
        const int slot = (wn * 4 + qcol) * 3;    // 8 threads x 3 entries per token
        int baseA = r0g * NCAND + slot;
        int baseB = r1g * NCAND + slot;
        redD[baseA] = bA1; redI[baseA] = iA1;
        redD[baseA + 1] = bA2; redI[baseA + 1] = iA2;
        redD[baseA + 2] = bA3; redI[baseA + 2] = iA3;
        redD[baseB] = bB1; redI[baseB] = iB1;
        redD[baseB + 1] = bB2; redI[baseB + 1] = iB2;
        redD[baseB + 2] = bB3; redI[baseB + 2] = iB3;
    }
    __syncthreads();

    // ---- exact fp32 refine: one thread per token (Z row via L1/L2) ----
    if (tid < BM) {
        const int tok = tid;
        float m1 = 3.4e38f;
#pragma unroll
        for (int e = 0; e < NCAND; ++e) m1 = fminf(m1, redD[tok * NCAND + e]);
        const float thr = m1 + MARGIN;
        const float nzt = nz_sm[tok];
        const float4* Zr = reinterpret_cast<const float4*>(Z) + (size_t)(m0 + tok) * 32;
        float bestd = 3.4e38f; int besti = KCODE;
        for (int e = 0; e < NCAND; ++e) {
            if (redD[tok * NCAND + e] <= thr) {
                const int id = redI[tok * NCAND + e];
                const float4* Er = reinterpret_cast<const float4*>(E) + (size_t)id * 32;
                float dot = 0.f;
#pragma unroll
                for (int q = 0; q < 32; ++q) {
                    float4 a = Zr[q], b = Er[q];
                    dot = fmaf(a.x, b.x, fmaf(a.y, b.y, fmaf(a.z, b.z, fmaf(a.w, b.w, dot))));
                }
                float de = fmaf(-2.f, dot, nzt) + ne_sm[id];   // reference association order
                if (de < bestd || (de == bestd && id < besti)) { bestd = de; besti = id; }
            }
        }
        ids_sm[tok] = besti;
        stg_cs_f1(idsf + m0 + tok, (float)besti);
        lt_sm[tok] = sqrtf(fmaxf(bestd, 0.f));   // ||z - z_q||^2 == dist_min exactly
    }
    __syncthreads();

    // z_q gather (codebook is L2-resident), streaming stores
    const float4* E4 = reinterpret_cast<const float4*>(E);
#pragma unroll
    for (int rr = 0; rr < 8; ++rr) {
        int ml = warp * 8 + rr;
        int id = ids_sm[ml];
        stg_cs_f4(zq + ((size_t)(m0 + ml) * 32 + lane) * 4, E4[(size_t)id * 32 + lane]);
    }

    // deterministic per-block loss partial (fixed serial order)
    if (tid == 0) {
        float s = 0.f;
        for (int i = 0; i < BM; ++i) s += lt_sm[i];
        g_partial[blockIdx.x] = s;
    }

    // ---- merged loss reduction: last CTA sums all partials (fixed tree) ----
    __shared__ int is_last;
    __threadfence();
    if (tid == 0) {
        unsigned old = atomicAdd(&g_done, 1u);
        is_last = (old == GRID_MAIN - 1) ? 1 : 0;
    }
    __syncthreads();
    if (is_last) {
        __threadfence();
        float* red = (float*)(sb + REDD_OFF);   // reuse candidate area
        float s = g_partial[tid] + g_partial[tid + 256]
                + g_partial[tid + 512] + g_partial[tid + 768];
        red[tid] = s;
        __syncthreads();
#pragma unroll
        for (int st = 128; st > 0; st >>= 1) {
            if (tid < st) red[tid] += red[tid + st];
            __syncthreads();
        }
        if (tid == 0) {
            out[LOSS_OFF] = 1.25f * (red[0] * (1.f / 65536.f));
            g_done = 0;   // reset for the next graph replay
        }
    }
}

extern "C" void kernel_launch(void* const* d_in, const int* in_sizes, int n_in,
                              void* d_out, int out_size) {
    (void)in_sizes; (void)n_in; (void)out_size;
    const float* Z = (const float*)d_in[0];   // z_e            [65536, 128]
    const float* E = (const float*)d_in[1];   // vecs_embedding [1024, 128]
    float* out = (float*)d_out;

    cudaFuncSetAttribute((const void*)vq_main,
                         cudaFuncAttributeMaxDynamicSharedMemorySize, SMEM_BYTES);

    prep_e<<<KCODE / 8, 256>>>(E);
    vq_main<<<GRID_MAIN, 256, SMEM_BYTES>>>(Z, E, out);
}